// round 10
// baseline (speedup 1.0000x reference)
#include <cuda_runtime.h>
#include <cuda_fp16.h>
#include <cstdint>
#include <cstddef>

// Problem constants (fixed for this problem; M derived at launch)
#define KDIM 4096
#define NDIM 11008
#define MMAX 8192
#define BM 128
#define BN 256
#define BK 64
#define STAGES 4
#define KT (KDIM / BK)        // 64
#define SA_STRIDE 72          // 64+8 halves -> 144B row stride (conflict-free ldmatrix)
#define SB_STRIDE 264         // 256+8 halves -> 528B row stride
#define A_STG (BM * SA_STRIDE)
#define B_STG (BK * SB_STRIDE)

// fp16 scratch: dequantized weights (scale folded), K-major [K][N]; fp16 copy of x.
static __device__ __half g_W[(size_t)KDIM * NDIM];   // 90.2 MB
static __device__ __half g_X[(size_t)MMAX * KDIM];   // 67.1 MB

// ---------------------------------------------------------------------------
// Phase 0: x (fp32 transport of fp16) -> fp16 g_X. Lossless.
// ---------------------------------------------------------------------------
__global__ void convert_x_kernel(const float* __restrict__ x, long long n) {
    long long i = ((long long)blockIdx.x * blockDim.x + threadIdx.x) * 8;
    if (i + 8 <= n) {
        float4 a = *reinterpret_cast<const float4*>(x + i);
        float4 b = *reinterpret_cast<const float4*>(x + i + 4);
        __half2 h[4];
        h[0] = __floats2half2_rn(a.x, a.y);
        h[1] = __floats2half2_rn(a.z, a.w);
        h[2] = __floats2half2_rn(b.x, b.y);
        h[3] = __floats2half2_rn(b.z, b.w);
        *reinterpret_cast<uint4*>(&g_X[i]) = *reinterpret_cast<uint4*>(h);
    }
}

// ---------------------------------------------------------------------------
// Phase 1: dequantize packed ternary -> fp16 g_W[k][n], scale folded (proven).
// ---------------------------------------------------------------------------
__global__ void dequant_kernel(const int32_t* __restrict__ pw,
                               const float* __restrict__ scales) {
    __shared__ __half sw[256][72];
    const int n0  = blockIdx.x * 64;
    const int kp0 = blockIdx.y * 16;
    const int t   = threadIdx.x;
    const int nl  = (t & 31) * 2;
    const int r0  = t >> 5;
    const __half2 k1025 = __float2half2_rn(1025.0f);

#pragma unroll
    for (int rr = r0; rr < 16; rr += 8) {
        const int kp = kp0 + rr;
        const int n  = n0 + nl;
        const int32_t va = pw[(size_t)kp * NDIM + n];
        const int32_t vb = pw[(size_t)kp * NDIM + n + 1];
        const int g = kp >> 3;
        const __half2 s2 = __floats2half2_rn(scales[(size_t)g * NDIM + n],
                                             scales[(size_t)g * NDIM + n + 1]);
#pragma unroll
        for (int j = 0; j < 16; j++) {
            uint32_t raw = 0x64006400u
                         | ((uint32_t)(va >> (2 * j)) & 3u)
                         | (((uint32_t)(vb >> (2 * j)) & 3u) << 16);
            __half2 h = __hmul2(__hsub2(*reinterpret_cast<__half2*>(&raw), k1025), s2);
            *reinterpret_cast<__half2*>(&sw[rr * 16 + j][nl]) = h;
        }
    }
    __syncthreads();

#pragma unroll
    for (int i = t; i < 2048; i += 256) {
        const int row = i >> 3, c = i & 7;
        *reinterpret_cast<uint4*>(&g_W[(size_t)(kp0 * 16 + row) * NDIM + n0 + c * 8]) =
            *reinterpret_cast<const uint4*>(&sw[row][c * 8]);
    }
}

// ---------------------------------------------------------------------------
// Phase 2: fp16 GEMM. fp16-accumulate HMMA (2x rate) with promotion of the
// fp16 partial accumulators into fp32 registers every 128 k (one scale group).
// C_f32 = float( half(acc32) + half(bias) ), reference rounding order.
// ---------------------------------------------------------------------------
#define CP_ASYNC16(dst, src) \
    asm volatile("cp.async.cg.shared.global [%0], [%1], 16;\n" :: "r"(dst), "l"(src))

__global__ __launch_bounds__(256, 1) void gemm_kernel(
    const float* __restrict__ bias, float* __restrict__ C, int M)
{
    extern __shared__ __half smem[];
    __half* sA = smem;                      // [STAGES][BM][SA_STRIDE]
    __half* sB = smem + STAGES * A_STG;     // [STAGES][BK][SB_STRIDE]

    const int tiles_n = NDIM / BN;          // 43
    const int tiles_m = M / BM;             // 64

    // GROUP_M=16 rasterization for L2 reuse of B.
    const int pid = blockIdx.x;
    const int GROUPM = 16;
    const int per_group = GROUPM * tiles_n;
    const int gid = pid / per_group;
    const int first_m = gid * GROUPM;
    const int gsz = min(GROUPM, tiles_m - first_m);
    const int rr  = pid % per_group;
    const int m0 = (first_m + rr % gsz) * BM;
    const int n0 = (rr / gsz) * BN;

    const int tid  = threadIdx.x;
    const int lane = tid & 31;
    const int warp = tid >> 5;
    const int wr = warp & 1;     // 0..1 -> 64-row slice
    const int wc = warp >> 1;    // 0..3 -> 64-col slice

    float acc[4][8][4];
#pragma unroll
    for (int a = 0; a < 4; a++)
#pragma unroll
        for (int b = 0; b < 8; b++)
#pragma unroll
            for (int c = 0; c < 4; c++) acc[a][b][c] = 0.f;

    uint32_t acc16[4][8][2];
#pragma unroll
    for (int a = 0; a < 4; a++)
#pragma unroll
        for (int b = 0; b < 8; b++) { acc16[a][b][0] = 0u; acc16[a][b][1] = 0u; }

    const uint32_t sA_base = (uint32_t)__cvta_generic_to_shared(sA);
    const uint32_t sB_base = (uint32_t)__cvta_generic_to_shared(sB);

    // gmem->smem 16B-chunk coordinates.
    const int a_row = tid >> 3;           // +32/iter (4 iters)
    const int a_c   = (tid & 7) * 8;
    const int b_row = tid >> 5;           // +8/iter (8 iters)
    const int b_c   = (tid & 31) * 8;

    const __half* Ag = g_X + (size_t)(m0 + a_row) * KDIM + a_c;
    const __half* Bg = g_W + (size_t)b_row * NDIM + n0 + b_c;

    auto load_stage = [&](int stage, int kt) {
        uint32_t da = sA_base + (uint32_t)(stage * A_STG + a_row * SA_STRIDE + a_c) * 2;
        const __half* ga = Ag + kt * BK;
#pragma unroll
        for (int i = 0; i < 4; i++) {
            CP_ASYNC16(da, ga);
            da += 32 * SA_STRIDE * 2;
            ga += (size_t)32 * KDIM;
        }
        uint32_t db = sB_base + (uint32_t)(stage * B_STG + b_row * SB_STRIDE + b_c) * 2;
        const __half* gb = Bg + (size_t)kt * BK * NDIM;
#pragma unroll
        for (int i = 0; i < 8; i++) {
            CP_ASYNC16(db, gb);
            db += 8 * SB_STRIDE * 2;
            gb += (size_t)8 * NDIM;
        }
        asm volatile("cp.async.commit_group;\n");
    };

    // ldmatrix lane-address components.
    const int lrow  = (lane & 7) + ((lane >> 3) & 1) * 8;
    const int acoff = ((lane >> 4) & 1) * 8;
    const int bkr   = (lane & 7) + ((lane >> 3) & 1) * 8;
    const int bnc   = wc * 64 + ((lane >> 4) & 1) * 8;

    uint32_t fa[4][4], fb[8][2];

    auto ldsm = [&](int stage, int ks) {
        const uint32_t pa = sA_base + (uint32_t)(stage * A_STG) * 2;
        const uint32_t pb = sB_base + (uint32_t)(stage * B_STG) * 2;
#pragma unroll
        for (int mi = 0; mi < 4; mi++) {
            const uint32_t addr = pa +
                (uint32_t)((wr * 64 + mi * 16 + lrow) * SA_STRIDE + ks * 16 + acoff) * 2;
            asm volatile("ldmatrix.sync.aligned.m8n8.x4.shared.b16 {%0,%1,%2,%3}, [%4];\n"
                : "=r"(fa[mi][0]), "=r"(fa[mi][1]), "=r"(fa[mi][2]), "=r"(fa[mi][3])
                : "r"(addr));
        }
#pragma unroll
        for (int ng = 0; ng < 4; ng++) {
            const uint32_t addr = pb +
                (uint32_t)((ks * 16 + bkr) * SB_STRIDE + bnc + ng * 16) * 2;
            uint32_t r0, r1, r2, r3;
            asm volatile("ldmatrix.sync.aligned.m8n8.x4.trans.shared.b16 {%0,%1,%2,%3}, [%4];\n"
                : "=r"(r0), "=r"(r1), "=r"(r2), "=r"(r3) : "r"(addr));
            fb[2 * ng][0] = r0;     fb[2 * ng][1] = r1;
            fb[2 * ng + 1][0] = r2; fb[2 * ng + 1][1] = r3;
        }
    };

    auto mma_all = [&]() {
#pragma unroll
        for (int mi = 0; mi < 4; mi++)
#pragma unroll
            for (int ni = 0; ni < 8; ni++) {
                asm volatile(
                    "mma.sync.aligned.m16n8k16.row.col.f16.f16.f16.f16 "
                    "{%0,%1}, {%2,%3,%4,%5}, {%6,%7}, {%0,%1};\n"
                    : "+r"(acc16[mi][ni][0]), "+r"(acc16[mi][ni][1])
                    : "r"(fa[mi][0]), "r"(fa[mi][1]), "r"(fa[mi][2]), "r"(fa[mi][3]),
                      "r"(fb[ni][0]), "r"(fb[ni][1]));
            }
    };

    auto promote = [&]() {
#pragma unroll
        for (int mi = 0; mi < 4; mi++)
#pragma unroll
            for (int ni = 0; ni < 8; ni++) {
                const __half2 h0 = *reinterpret_cast<__half2*>(&acc16[mi][ni][0]);
                const __half2 h1 = *reinterpret_cast<__half2*>(&acc16[mi][ni][1]);
                const float2 f0 = __half22float2(h0);
                const float2 f1 = __half22float2(h1);
                acc[mi][ni][0] += f0.x;
                acc[mi][ni][1] += f0.y;
                acc[mi][ni][2] += f1.x;
                acc[mi][ni][3] += f1.y;
                acc16[mi][ni][0] = 0u;
                acc16[mi][ni][1] = 0u;
            }
    };

    // Prologue: fill STAGES-1 stages, wait for stage 0.
#pragma unroll
    for (int s = 0; s < STAGES - 1; s++) load_stage(s, s);
    asm volatile("cp.async.wait_group %0;\n" :: "n"(STAGES - 2) : "memory");
    __syncthreads();

    for (int kt = 0; kt < KT; kt++) {
        const int stage = kt & (STAGES - 1);
#pragma unroll
        for (int ks = 0; ks < 4; ks++) {
            if (ks == 0) {
                if (kt + STAGES - 1 < KT)
                    load_stage((kt + STAGES - 1) & (STAGES - 1), kt + STAGES - 1);
                else
                    asm volatile("cp.async.commit_group;\n");  // keep group count fixed
            }
            ldsm(stage, ks);
            mma_all();
            if (ks == 3) {
                asm volatile("cp.async.wait_group %0;\n" :: "n"(STAGES - 2) : "memory");
                __syncthreads();
            }
        }
        if (kt & 1) promote();   // every 128 k = one scale group
    }

    // Epilogue: half(acc32) + half(bias) in fp16 (reference rounding), widen to fp32.
#pragma unroll
    for (int mi = 0; mi < 4; mi++) {
        const int row = m0 + wr * 64 + mi * 16 + (lane >> 2);
#pragma unroll
        for (int ni = 0; ni < 8; ni++) {
            const int col = n0 + wc * 64 + ni * 8 + (lane & 3) * 2;
            const float2 bf32 = *reinterpret_cast<const float2*>(bias + col);
            const __half2 bv = __floats2half2_rn(bf32.x, bf32.y);
            __half2 v0 = __hadd2(__floats2half2_rn(acc[mi][ni][0], acc[mi][ni][1]), bv);
            __half2 v1 = __hadd2(__floats2half2_rn(acc[mi][ni][2], acc[mi][ni][3]), bv);
            float2 o0 = __half22float2(v0);
            float2 o1 = __half22float2(v1);
            *reinterpret_cast<float2*>(C + (size_t)row * NDIM + col) = o0;
            *reinterpret_cast<float2*>(C + (size_t)(row + 8) * NDIM + col) = o1;
        }
    }
}

// ---------------------------------------------------------------------------
extern "C" void kernel_launch(void* const* d_in, const int* in_sizes, int n_in,
                              void* d_out, int out_size) {
    const float*   x      = (const float*)d_in[0];
    const int32_t* pw     = (const int32_t*)d_in[1];
    const float*   scales = (const float*)d_in[2];
    const float*   bias   = (const float*)d_in[3];
    float*         out    = (float*)d_out;
    const int M = in_sizes[0] / KDIM;   // 8192

    const long long nx = (long long)M * KDIM;
    convert_x_kernel<<<(int)((nx / 8 + 255) / 256), 256>>>(x, nx);

    dequant_kernel<<<dim3(NDIM / 64, KDIM / 256), 256>>>(pw, scales);

    const int smem_bytes = STAGES * (A_STG + B_STG) * (int)sizeof(__half);  // 208896
    cudaFuncSetAttribute(gemm_kernel, cudaFuncAttributeMaxDynamicSharedMemorySize,
                         smem_bytes);
    const int grid = (M / BM) * (NDIM / BN);
    gemm_kernel<<<grid, 256, smem_bytes>>>(bias, out, M);
}

// round 11
// speedup vs baseline: 1.5234x; 1.5234x over previous
#include <cuda_runtime.h>
#include <cuda_fp16.h>
#include <cstdint>
#include <cstddef>

// Problem constants (fixed for this problem; M derived at launch)
#define KDIM 4096
#define NDIM 11008
#define MMAX 8192
#define BM 128
#define BN 256
#define BK 64
#define STAGES 4
#define KT (KDIM / BK)        // 64
#define SA_STRIDE 72          // 64+8 halves -> 144B row stride (conflict-free ldmatrix)
#define SB_STRIDE 264         // 256+8 halves -> 528B row stride
#define A_STG (BM * SA_STRIDE)
#define B_STG (BK * SB_STRIDE)

// fp16 scratch: dequantized weights (scale folded), K-major [K][N]; fp16 copy of x.
static __device__ __half g_W[(size_t)KDIM * NDIM];   // 90.2 MB
static __device__ __half g_X[(size_t)MMAX * KDIM];   // 67.1 MB

// ---------------------------------------------------------------------------
// Phase 0: x (fp32 transport of fp16) -> fp16 g_X. Lossless.
// ---------------------------------------------------------------------------
__global__ void convert_x_kernel(const float* __restrict__ x, long long n) {
    long long i = ((long long)blockIdx.x * blockDim.x + threadIdx.x) * 8;
    if (i + 8 <= n) {
        float4 a = *reinterpret_cast<const float4*>(x + i);
        float4 b = *reinterpret_cast<const float4*>(x + i + 4);
        __half2 h[4];
        h[0] = __floats2half2_rn(a.x, a.y);
        h[1] = __floats2half2_rn(a.z, a.w);
        h[2] = __floats2half2_rn(b.x, b.y);
        h[3] = __floats2half2_rn(b.z, b.w);
        *reinterpret_cast<uint4*>(&g_X[i]) = *reinterpret_cast<uint4*>(h);
    }
}

// ---------------------------------------------------------------------------
// Phase 1: dequantize packed ternary -> fp16 g_W[k][n], scale folded.
// LUT version: interleave code bits of adjacent-n ints (va, vb) so each 4-bit
// nibble indexes a 16-entry half2 LUT of exact (code-1) values in {-1,0,+1};
// hmul2 by the fp16 scale pair gives {-s,0,+s} exactly -> bit-identical to
// the reference's fp16 dequant. ~3 ops per half2 output vs ~6 before.
// Block: 16 kp-rows (256 k) x 64 n-cols, SMEM transpose for coalesced output.
// ---------------------------------------------------------------------------
__global__ void dequant_kernel(const int32_t* __restrict__ pw,
                               const float* __restrict__ scales) {
    __shared__ __half2 lut[16];
    __shared__ __half sw[256][72];   // row stride 144B (16B-aligned)
    const int n0  = blockIdx.x * 64;
    const int kp0 = blockIdx.y * 16;
    const int t   = threadIdx.x;
    const int nl  = (t & 31) * 2;    // local n (even)
    const int r0  = t >> 5;          // 0..7

    if (t < 16)
        lut[t] = __halves2half2(__int2half_rn((t & 3) - 1),
                                __int2half_rn((t >> 2) - 1));
    __syncthreads();

#pragma unroll
    for (int rr = r0; rr < 16; rr += 8) {
        const int kp = kp0 + rr;
        const int n  = n0 + nl;
        const int2  vab = *reinterpret_cast<const int2*>(&pw[(size_t)kp * NDIM + n]);
        const uint32_t va = (uint32_t)vab.x;   // codes for column n
        const uint32_t vb = (uint32_t)vab.y;   // codes for column n+1
        const int g = kp >> 3;                 // k-group = (kp*16)/128
        const float2 sf = *reinterpret_cast<const float2*>(&scales[(size_t)g * NDIM + n]);
        const __half2 s2 = __floats2half2_rn(sf.x, sf.y);

        // nibble m of w1 = (va code 2m, vb code 2m); of w2 = (va code 2m+1, vb code 2m+1)
        const uint32_t w1 = (va & 0x33333333u) | ((vb & 0x33333333u) << 2);
        const uint32_t w2 = ((va >> 2) & 0x33333333u) | (((vb >> 2) & 0x33333333u) << 2);

        __half* row_base = &sw[rr * 16][0];
#pragma unroll
        for (int m = 0; m < 8; m++) {
            const __half2 he = __hmul2(lut[(w1 >> (4 * m)) & 0xFu], s2);
            const __half2 ho = __hmul2(lut[(w2 >> (4 * m)) & 0xFu], s2);
            *reinterpret_cast<__half2*>(row_base + (2 * m) * 72 + nl)     = he;
            *reinterpret_cast<__half2*>(row_base + (2 * m + 1) * 72 + nl) = ho;
        }
    }
    __syncthreads();

    // Coalesced 16B writes: 256 rows x 64 halves = 2048 uint4 chunks.
#pragma unroll
    for (int i = t; i < 2048; i += 256) {
        const int row = i >> 3, c = i & 7;
        *reinterpret_cast<uint4*>(&g_W[(size_t)(kp0 * 16 + row) * NDIM + n0 + c * 8]) =
            *reinterpret_cast<const uint4*>(&sw[row][c * 8]);
    }
}

// ---------------------------------------------------------------------------
// Phase 2: fp16 GEMM, fp32 accumulation, multi-stage cp.async + reg pipeline.
// (Unchanged from the proven 1540us kernel.)
// C_f32 = float( half(acc) + half(bias) ), reference rounding order.
// ---------------------------------------------------------------------------
#define CP_ASYNC16(dst, src) \
    asm volatile("cp.async.cg.shared.global [%0], [%1], 16;\n" :: "r"(dst), "l"(src))

__global__ __launch_bounds__(256, 1) void gemm_kernel(
    const float* __restrict__ bias, float* __restrict__ C, int M)
{
    extern __shared__ __half smem[];
    __half* sA = smem;                      // [STAGES][BM][SA_STRIDE]
    __half* sB = smem + STAGES * A_STG;     // [STAGES][BK][SB_STRIDE]

    const int tiles_n = NDIM / BN;          // 43
    const int tiles_m = M / BM;             // 64

    // GROUP_M=16 rasterization: B re-read from DRAM only tiles_m/16 = 4 times.
    const int pid = blockIdx.x;
    const int GROUPM = 16;
    const int per_group = GROUPM * tiles_n;
    const int gid = pid / per_group;
    const int first_m = gid * GROUPM;
    const int gsz = min(GROUPM, tiles_m - first_m);
    const int rr  = pid % per_group;
    const int m0 = (first_m + rr % gsz) * BM;
    const int n0 = (rr / gsz) * BN;

    const int tid  = threadIdx.x;
    const int lane = tid & 31;
    const int warp = tid >> 5;
    const int wr = warp & 1;     // 0..1 -> 64-row slice
    const int wc = warp >> 1;    // 0..3 -> 64-col slice

    float acc[4][8][4];
#pragma unroll
    for (int a = 0; a < 4; a++)
#pragma unroll
        for (int b = 0; b < 8; b++)
#pragma unroll
            for (int c = 0; c < 4; c++) acc[a][b][c] = 0.f;

    const uint32_t sA_base = (uint32_t)__cvta_generic_to_shared(sA);
    const uint32_t sB_base = (uint32_t)__cvta_generic_to_shared(sB);

    // gmem->smem 16B-chunk coordinates.
    const int a_row = tid >> 3;           // +32/iter (4 iters)
    const int a_c   = (tid & 7) * 8;
    const int b_row = tid >> 5;           // +8/iter (8 iters)
    const int b_c   = (tid & 31) * 8;

    const __half* Ag = g_X + (size_t)(m0 + a_row) * KDIM + a_c;
    const __half* Bg = g_W + (size_t)b_row * NDIM + n0 + b_c;

    auto load_stage = [&](int stage, int kt) {
        uint32_t da = sA_base + (uint32_t)(stage * A_STG + a_row * SA_STRIDE + a_c) * 2;
        const __half* ga = Ag + kt * BK;
#pragma unroll
        for (int i = 0; i < 4; i++) {
            CP_ASYNC16(da, ga);
            da += 32 * SA_STRIDE * 2;
            ga += (size_t)32 * KDIM;
        }
        uint32_t db = sB_base + (uint32_t)(stage * B_STG + b_row * SB_STRIDE + b_c) * 2;
        const __half* gb = Bg + (size_t)kt * BK * NDIM;
#pragma unroll
        for (int i = 0; i < 8; i++) {
            CP_ASYNC16(db, gb);
            db += 8 * SB_STRIDE * 2;
            gb += (size_t)8 * NDIM;
        }
        asm volatile("cp.async.commit_group;\n");
    };

    // ldmatrix lane-address components.
    const int lrow  = (lane & 7) + ((lane >> 3) & 1) * 8;
    const int acoff = ((lane >> 4) & 1) * 8;
    const int bkr   = (lane & 7) + ((lane >> 3) & 1) * 8;
    const int bnc   = wc * 64 + ((lane >> 4) & 1) * 8;

    uint32_t fa[2][4][4], fb[2][8][2];

    auto ldsm = [&](int stage, int ks, int buf) {
        const uint32_t pa = sA_base + (uint32_t)(stage * A_STG) * 2;
        const uint32_t pb = sB_base + (uint32_t)(stage * B_STG) * 2;
#pragma unroll
        for (int mi = 0; mi < 4; mi++) {
            const uint32_t addr = pa +
                (uint32_t)((wr * 64 + mi * 16 + lrow) * SA_STRIDE + ks * 16 + acoff) * 2;
            asm volatile("ldmatrix.sync.aligned.m8n8.x4.shared.b16 {%0,%1,%2,%3}, [%4];\n"
                : "=r"(fa[buf][mi][0]), "=r"(fa[buf][mi][1]),
                  "=r"(fa[buf][mi][2]), "=r"(fa[buf][mi][3])
                : "r"(addr));
        }
#pragma unroll
        for (int ng = 0; ng < 4; ng++) {
            const uint32_t addr = pb +
                (uint32_t)((ks * 16 + bkr) * SB_STRIDE + bnc + ng * 16) * 2;
            uint32_t r0, r1, r2, r3;
            asm volatile("ldmatrix.sync.aligned.m8n8.x4.trans.shared.b16 {%0,%1,%2,%3}, [%4];\n"
                : "=r"(r0), "=r"(r1), "=r"(r2), "=r"(r3) : "r"(addr));
            fb[buf][2 * ng][0] = r0;     fb[buf][2 * ng][1] = r1;
            fb[buf][2 * ng + 1][0] = r2; fb[buf][2 * ng + 1][1] = r3;
        }
    };

    auto mma_all = [&](int buf) {
#pragma unroll
        for (int mi = 0; mi < 4; mi++)
#pragma unroll
            for (int ni = 0; ni < 8; ni++) {
                asm volatile(
                    "mma.sync.aligned.m16n8k16.row.col.f32.f16.f16.f32 "
                    "{%0,%1,%2,%3}, {%4,%5,%6,%7}, {%8,%9}, {%0,%1,%2,%3};\n"
                    : "+f"(acc[mi][ni][0]), "+f"(acc[mi][ni][1]),
                      "+f"(acc[mi][ni][2]), "+f"(acc[mi][ni][3])
                    : "r"(fa[buf][mi][0]), "r"(fa[buf][mi][1]),
                      "r"(fa[buf][mi][2]), "r"(fa[buf][mi][3]),
                      "r"(fb[buf][ni][0]), "r"(fb[buf][ni][1]));
            }
    };

    // Prologue: fill STAGES-1 stages, wait for stage 0, prime fragments.
#pragma unroll
    for (int s = 0; s < STAGES - 1; s++) load_stage(s, s);
    asm volatile("cp.async.wait_group %0;\n" :: "n"(STAGES - 2) : "memory");
    __syncthreads();
    ldsm(0, 0, 0);

    for (int kt = 0; kt < KT; kt++) {
        const int stage = kt & (STAGES - 1);
#pragma unroll
        for (int ks = 0; ks < 4; ks++) {
            const int cur = ks & 1, nxt = cur ^ 1;
            if (ks == 0) {
                if (kt + STAGES - 1 < KT)
                    load_stage((kt + STAGES - 1) & (STAGES - 1), kt + STAGES - 1);
                else
                    asm volatile("cp.async.commit_group;\n");  // keep group count fixed
            }
            if (ks < 3) {
                ldsm(stage, ks + 1, nxt);
            } else {
                asm volatile("cp.async.wait_group %0;\n" :: "n"(STAGES - 2) : "memory");
                __syncthreads();
                if (kt + 1 < KT) ldsm((kt + 1) & (STAGES - 1), 0, nxt);
            }
            mma_all(cur);
        }
    }

    // Epilogue: half(acc) + half(bias) in fp16 (reference rounding), widen to fp32.
#pragma unroll
    for (int mi = 0; mi < 4; mi++) {
        const int row = m0 + wr * 64 + mi * 16 + (lane >> 2);
#pragma unroll
        for (int ni = 0; ni < 8; ni++) {
            const int col = n0 + wc * 64 + ni * 8 + (lane & 3) * 2;
            const float2 bf32 = *reinterpret_cast<const float2*>(bias + col);
            const __half2 bv = __floats2half2_rn(bf32.x, bf32.y);
            __half2 v0 = __hadd2(__floats2half2_rn(acc[mi][ni][0], acc[mi][ni][1]), bv);
            __half2 v1 = __hadd2(__floats2half2_rn(acc[mi][ni][2], acc[mi][ni][3]), bv);
            float2 o0 = __half22float2(v0);
            float2 o1 = __half22float2(v1);
            *reinterpret_cast<float2*>(C + (size_t)row * NDIM + col) = o0;
            *reinterpret_cast<float2*>(C + (size_t)(row + 8) * NDIM + col) = o1;
        }
    }
}

// ---------------------------------------------------------------------------
extern "C" void kernel_launch(void* const* d_in, const int* in_sizes, int n_in,
                              void* d_out, int out_size) {
    const float*   x      = (const float*)d_in[0];
    const int32_t* pw     = (const int32_t*)d_in[1];
    const float*   scales = (const float*)d_in[2];
    const float*   bias   = (const float*)d_in[3];
    float*         out    = (float*)d_out;
    const int M = in_sizes[0] / KDIM;   // 8192

    const long long nx = (long long)M * KDIM;
    convert_x_kernel<<<(int)((nx / 8 + 255) / 256), 256>>>(x, nx);

    dequant_kernel<<<dim3(NDIM / 64, KDIM / 256), 256>>>(pw, scales);

    const int smem_bytes = STAGES * (A_STG + B_STG) * (int)sizeof(__half);  // 208896
    cudaFuncSetAttribute(gemm_kernel, cudaFuncAttributeMaxDynamicSharedMemorySize,
                         smem_bytes);
    const int grid = (M / BM) * (NDIM / BN);
    gemm_kernel<<<grid, 256, smem_bytes>>>(bias, out, M);
}

// round 12
// speedup vs baseline: 1.5915x; 1.0447x over previous
#include <cuda_runtime.h>
#include <cuda_fp16.h>
#include <cstdint>
#include <cstddef>

// Problem constants (fixed for this problem; M derived at launch)
#define KDIM 4096
#define NDIM 11008
#define MMAX 8192
#define BM 128
#define BN 256
#define BK 64
#define STAGES 4
#define KT (KDIM / BK)        // 64
#define SA_STRIDE 72          // 64+8 halves -> 144B row stride (conflict-free ldmatrix)
#define SB_STRIDE 264         // 256+8 halves -> 528B row stride
#define A_STG (BM * SA_STRIDE)
#define B_STG (BK * SB_STRIDE)
#define DQ_BLOCKS ((NDIM / 64) * (KDIM / 256))   // 172*16 = 2752

// fp16 scratch: dequantized weights (scale folded), K-major [K][N]; fp16 copy of x.
static __device__ __half g_W[(size_t)KDIM * NDIM];   // 90.2 MB
static __device__ __half g_X[(size_t)MMAX * KDIM];   // 67.1 MB

// ---------------------------------------------------------------------------
// Phase 1 (fused): blocks [0, DQ_BLOCKS) dequantize packed ternary -> g_W;
// blocks [DQ_BLOCKS, ...) convert x f32->f16 -> g_X. Overlaps the two
// DRAM-bound preprocessing passes in one launch.
// Dequant math (proven bit-identical to reference): 16-entry half2 LUT of
// exact (code-1) in {-1,0,+1}; hmul2 by fp16 scale gives {-s,0,+s} exactly.
// ---------------------------------------------------------------------------
__global__ __launch_bounds__(256) void prep_kernel(
    const float* __restrict__ x, const int32_t* __restrict__ pw,
    const float* __restrict__ scales, long long nx)
{
    __shared__ __half2 lut[16];
    __shared__ __half sw[256][72];   // row stride 144B (16B-aligned)
    const int t = threadIdx.x;

    if (blockIdx.x >= DQ_BLOCKS) {
        // ---- convert branch ----
        long long i = ((long long)(blockIdx.x - DQ_BLOCKS) * 256 + t) * 8;
        if (i + 8 <= nx) {
            float4 a = *reinterpret_cast<const float4*>(x + i);
            float4 b = *reinterpret_cast<const float4*>(x + i + 4);
            __half2 h[4];
            h[0] = __floats2half2_rn(a.x, a.y);
            h[1] = __floats2half2_rn(a.z, a.w);
            h[2] = __floats2half2_rn(b.x, b.y);
            h[3] = __floats2half2_rn(b.z, b.w);
            *reinterpret_cast<uint4*>(&g_X[i]) = *reinterpret_cast<uint4*>(h);
        }
        return;
    }

    // ---- dequant branch ----
    const int n0  = (blockIdx.x % (NDIM / 64)) * 64;
    const int kp0 = (blockIdx.x / (NDIM / 64)) * 16;
    const int nl  = (t & 31) * 2;    // local n (even)
    const int r0  = t >> 5;          // 0..7

    if (t < 16)
        lut[t] = __halves2half2(__int2half_rn((t & 3) - 1),
                                __int2half_rn((t >> 2) - 1));
    __syncthreads();

#pragma unroll
    for (int rr = r0; rr < 16; rr += 8) {
        const int kp = kp0 + rr;
        const int n  = n0 + nl;
        const int2  vab = *reinterpret_cast<const int2*>(&pw[(size_t)kp * NDIM + n]);
        const uint32_t va = (uint32_t)vab.x;
        const uint32_t vb = (uint32_t)vab.y;
        const int g = kp >> 3;       // k-group = (kp*16)/128
        const float2 sf = *reinterpret_cast<const float2*>(&scales[(size_t)g * NDIM + n]);
        const __half2 s2 = __floats2half2_rn(sf.x, sf.y);

        const uint32_t w1 = (va & 0x33333333u) | ((vb & 0x33333333u) << 2);
        const uint32_t w2 = ((va >> 2) & 0x33333333u) | (((vb >> 2) & 0x33333333u) << 2);

        __half* row_base = &sw[rr * 16][0];
#pragma unroll
        for (int m = 0; m < 8; m++) {
            const __half2 he = __hmul2(lut[(w1 >> (4 * m)) & 0xFu], s2);
            const __half2 ho = __hmul2(lut[(w2 >> (4 * m)) & 0xFu], s2);
            *reinterpret_cast<__half2*>(row_base + (2 * m) * 72 + nl)     = he;
            *reinterpret_cast<__half2*>(row_base + (2 * m + 1) * 72 + nl) = ho;
        }
    }
    __syncthreads();

#pragma unroll
    for (int i = t; i < 2048; i += 256) {
        const int row = i >> 3, c = i & 7;
        *reinterpret_cast<uint4*>(&g_W[(size_t)(kp0 * 16 + row) * NDIM + n0 + c * 8]) =
            *reinterpret_cast<const uint4*>(&sw[row][c * 8]);
    }
}

// ---------------------------------------------------------------------------
// Phase 2: fp16 GEMM, fp32 accumulation, multi-stage cp.async + reg pipeline.
// cp.async issues spread across ks (A @ks0, B/2 @ks1, B/2 @ks2 + commit).
// C_f32 = float( half(acc) + half(bias) ), reference rounding order.
// ---------------------------------------------------------------------------
#define CP_ASYNC16(dst, src) \
    asm volatile("cp.async.cg.shared.global [%0], [%1], 16;\n" :: "r"(dst), "l"(src))

__global__ __launch_bounds__(256, 1) void gemm_kernel(
    const float* __restrict__ bias, float* __restrict__ C, int M)
{
    extern __shared__ __half smem[];
    __half* sA = smem;                      // [STAGES][BM][SA_STRIDE]
    __half* sB = smem + STAGES * A_STG;     // [STAGES][BK][SB_STRIDE]

    const int tiles_n = NDIM / BN;          // 43
    const int tiles_m = M / BM;             // 64

    // GROUP_M=16 rasterization: B re-read from DRAM only tiles_m/16 = 4 times.
    const int pid = blockIdx.x;
    const int GROUPM = 16;
    const int per_group = GROUPM * tiles_n;
    const int gid = pid / per_group;
    const int first_m = gid * GROUPM;
    const int gsz = min(GROUPM, tiles_m - first_m);
    const int rr  = pid % per_group;
    const int m0 = (first_m + rr % gsz) * BM;
    const int n0 = (rr / gsz) * BN;

    const int tid  = threadIdx.x;
    const int lane = tid & 31;
    const int warp = tid >> 5;
    const int wr = warp & 1;     // 0..1 -> 64-row slice
    const int wc = warp >> 1;    // 0..3 -> 64-col slice

    float acc[4][8][4];
#pragma unroll
    for (int a = 0; a < 4; a++)
#pragma unroll
        for (int b = 0; b < 8; b++)
#pragma unroll
            for (int c = 0; c < 4; c++) acc[a][b][c] = 0.f;

    const uint32_t sA_base = (uint32_t)__cvta_generic_to_shared(sA);
    const uint32_t sB_base = (uint32_t)__cvta_generic_to_shared(sB);

    // gmem->smem 16B-chunk coordinates.
    const int a_row = tid >> 3;           // +32/iter (4 iters)
    const int a_c   = (tid & 7) * 8;
    const int b_row = tid >> 5;           // +8/iter (8 iters)
    const int b_c   = (tid & 31) * 8;

    const __half* Ag = g_X + (size_t)(m0 + a_row) * KDIM + a_c;
    const __half* Bg = g_W + (size_t)b_row * NDIM + n0 + b_c;

    auto load_A = [&](int stage, int kt) {
        uint32_t da = sA_base + (uint32_t)(stage * A_STG + a_row * SA_STRIDE + a_c) * 2;
        const __half* ga = Ag + kt * BK;
#pragma unroll
        for (int i = 0; i < 4; i++) {
            CP_ASYNC16(da, ga);
            da += 32 * SA_STRIDE * 2;
            ga += (size_t)32 * KDIM;
        }
    };
    auto load_B = [&](int stage, int kt, int half) {
        uint32_t db = sB_base + (uint32_t)(stage * B_STG + (b_row + half * 32) * SB_STRIDE + b_c) * 2;
        const __half* gb = Bg + (size_t)(kt * BK + half * 32) * NDIM;
#pragma unroll
        for (int i = 0; i < 4; i++) {
            CP_ASYNC16(db, gb);
            db += 8 * SB_STRIDE * 2;
            gb += (size_t)8 * NDIM;
        }
    };

    // ldmatrix lane-address components.
    const int lrow  = (lane & 7) + ((lane >> 3) & 1) * 8;
    const int acoff = ((lane >> 4) & 1) * 8;
    const int bkr   = (lane & 7) + ((lane >> 3) & 1) * 8;
    const int bnc   = wc * 64 + ((lane >> 4) & 1) * 8;

    uint32_t fa[2][4][4], fb[2][8][2];

    auto ldsm = [&](int stage, int ks, int buf) {
        const uint32_t pa = sA_base + (uint32_t)(stage * A_STG) * 2;
        const uint32_t pb = sB_base + (uint32_t)(stage * B_STG) * 2;
#pragma unroll
        for (int mi = 0; mi < 4; mi++) {
            const uint32_t addr = pa +
                (uint32_t)((wr * 64 + mi * 16 + lrow) * SA_STRIDE + ks * 16 + acoff) * 2;
            asm volatile("ldmatrix.sync.aligned.m8n8.x4.shared.b16 {%0,%1,%2,%3}, [%4];\n"
                : "=r"(fa[buf][mi][0]), "=r"(fa[buf][mi][1]),
                  "=r"(fa[buf][mi][2]), "=r"(fa[buf][mi][3])
                : "r"(addr));
        }
#pragma unroll
        for (int ng = 0; ng < 4; ng++) {
            const uint32_t addr = pb +
                (uint32_t)((ks * 16 + bkr) * SB_STRIDE + bnc + ng * 16) * 2;
            uint32_t r0, r1, r2, r3;
            asm volatile("ldmatrix.sync.aligned.m8n8.x4.trans.shared.b16 {%0,%1,%2,%3}, [%4];\n"
                : "=r"(r0), "=r"(r1), "=r"(r2), "=r"(r3) : "r"(addr));
            fb[buf][2 * ng][0] = r0;     fb[buf][2 * ng][1] = r1;
            fb[buf][2 * ng + 1][0] = r2; fb[buf][2 * ng + 1][1] = r3;
        }
    };

    auto mma_all = [&](int buf) {
#pragma unroll
        for (int mi = 0; mi < 4; mi++)
#pragma unroll
            for (int ni = 0; ni < 8; ni++) {
                asm volatile(
                    "mma.sync.aligned.m16n8k16.row.col.f32.f16.f16.f32 "
                    "{%0,%1,%2,%3}, {%4,%5,%6,%7}, {%8,%9}, {%0,%1,%2,%3};\n"
                    : "+f"(acc[mi][ni][0]), "+f"(acc[mi][ni][1]),
                      "+f"(acc[mi][ni][2]), "+f"(acc[mi][ni][3])
                    : "r"(fa[buf][mi][0]), "r"(fa[buf][mi][1]),
                      "r"(fa[buf][mi][2]), "r"(fa[buf][mi][3]),
                      "r"(fb[buf][ni][0]), "r"(fb[buf][ni][1]));
            }
    };

    // Prologue: fill STAGES-1 stages, wait for stage 0, prime fragments.
#pragma unroll
    for (int s = 0; s < STAGES - 1; s++) {
        load_A(s, s);
        load_B(s, s, 0);
        load_B(s, s, 1);
        asm volatile("cp.async.commit_group;\n");
    }
    asm volatile("cp.async.wait_group %0;\n" :: "n"(STAGES - 2) : "memory");
    __syncthreads();
    ldsm(0, 0, 0);

    for (int kt = 0; kt < KT; kt++) {
        const int stage = kt & (STAGES - 1);
        const int lkt = kt + STAGES - 1;
        const bool do_load = lkt < KT;
        const int lstage = lkt & (STAGES - 1);
#pragma unroll
        for (int ks = 0; ks < 4; ks++) {
            const int cur = ks & 1, nxt = cur ^ 1;
            if (ks == 0 && do_load) load_A(lstage, lkt);
            if (ks == 1 && do_load) load_B(lstage, lkt, 0);
            if (ks == 2) {
                if (do_load) load_B(lstage, lkt, 1);
                asm volatile("cp.async.commit_group;\n");   // one group per kt
            }
            if (ks < 3) {
                ldsm(stage, ks + 1, nxt);
            } else {
                asm volatile("cp.async.wait_group %0;\n" :: "n"(STAGES - 2) : "memory");
                __syncthreads();
                if (kt + 1 < KT) ldsm((kt + 1) & (STAGES - 1), 0, nxt);
            }
            mma_all(cur);
        }
    }

    // Epilogue: half(acc) + half(bias) in fp16 (reference rounding), widen to fp32.
#pragma unroll
    for (int mi = 0; mi < 4; mi++) {
        const int row = m0 + wr * 64 + mi * 16 + (lane >> 2);
#pragma unroll
        for (int ni = 0; ni < 8; ni++) {
            const int col = n0 + wc * 64 + ni * 8 + (lane & 3) * 2;
            const float2 bf32 = *reinterpret_cast<const float2*>(bias + col);
            const __half2 bv = __floats2half2_rn(bf32.x, bf32.y);
            __half2 v0 = __hadd2(__floats2half2_rn(acc[mi][ni][0], acc[mi][ni][1]), bv);
            __half2 v1 = __hadd2(__floats2half2_rn(acc[mi][ni][2], acc[mi][ni][3]), bv);
            float2 o0 = __half22float2(v0);
            float2 o1 = __half22float2(v1);
            *reinterpret_cast<float2*>(C + (size_t)row * NDIM + col) = o0;
            *reinterpret_cast<float2*>(C + (size_t)(row + 8) * NDIM + col) = o1;
        }
    }
}

// ---------------------------------------------------------------------------
extern "C" void kernel_launch(void* const* d_in, const int* in_sizes, int n_in,
                              void* d_out, int out_size) {
    const float*   x      = (const float*)d_in[0];
    const int32_t* pw     = (const int32_t*)d_in[1];
    const float*   scales = (const float*)d_in[2];
    const float*   bias   = (const float*)d_in[3];
    float*         out    = (float*)d_out;
    const int M = in_sizes[0] / KDIM;   // 8192

    const long long nx = (long long)M * KDIM;
    const int cv_blocks = (int)((nx / 8 + 255) / 256);
    prep_kernel<<<DQ_BLOCKS + cv_blocks, 256>>>(x, pw, scales, nx);

    const int smem_bytes = STAGES * (A_STG + B_STG) * (int)sizeof(__half);  // 208896
    cudaFuncSetAttribute(gemm_kernel, cudaFuncAttributeMaxDynamicSharedMemorySize,
                         smem_bytes);
    const int grid = (M / BM) * (NDIM / BN);
    gemm_kernel<<<grid, 256, smem_bytes>>>(bias, out, M);
}